// round 1
// baseline (speedup 1.0000x reference)
#include <cuda_runtime.h>
#include <math.h>

#define BB 4
#define LL 256
#define DD 768
#define HH 12
#define HD 64
#define NSTEPS 6
#define SMAX (LL*NSTEPS)   // 1536
#define NROW (BB*LL)       // 1024
#define CC 50257

// ---------------- scratch (device globals; no allocation) ----------------
__device__ float g_hbuf[(size_t)BB*LL*7*DD];      // [B,L,7,D] slot buffer
__device__ float g_xk  [(size_t)BB*SMAX*DD];      // keys/values input rows (contiguous)
__device__ float g_kv  [(size_t)BB*SMAX*2*DD];    // [B*S, 1536] = K|V per row
__device__ float g_xq  [(size_t)NROW*DD];         // query-row input (also head input)
__device__ float g_q   [(size_t)NROW*DD];         // projected Q
__device__ float g_attno[(size_t)NROW*DD];        // attention output (merged heads)
__device__ float g_tmp [(size_t)NROW*DD];
__device__ float g_y   [(size_t)NROW*DD];
__device__ float g_ff  [(size_t)NROW*DD];

// ---------------- small elementwise kernels ----------------
__global__ void embed_kernel(const int* __restrict__ x, const float* __restrict__ emb,
                             const float* __restrict__ pos) {
  int n = blockIdx.x;                 // b*LL + l
  int l = n % LL;
  int tok = x[n];
  const float* e = emb + (size_t)tok * DD;
  const float* p = pos + (size_t)l * DD;
  float* dst = g_hbuf + (size_t)n * 7 * DD;   // slot 0
  for (int i = threadIdx.x; i < DD; i += blockDim.x) dst[i] = e[i] + p[i];
}

__global__ void add_time_kernel(const float* __restrict__ te, int step) {
  int n = blockIdx.x;                 // b*LL + l ; slot = step (= t-1)
  float* dst = g_hbuf + ((size_t)n * 7 + step) * DD;
  const float* s = te + (size_t)step * DD;
  for (int i = threadIdx.x; i < DD; i += blockDim.x) dst[i] += s[i];
}

__global__ void gather_xk_kernel(int t) {
  int n = blockIdx.x;                 // row in [0, B*L*t)
  int st = LL * t;
  int b = n / st; int s = n % st; int l = s / t; int slot = s % t;
  const float* src = g_hbuf + ((size_t)(b * LL + l) * 7 + slot) * DD;
  float* dst = g_xk + (size_t)n * DD;
  for (int i = threadIdx.x; i < DD; i += blockDim.x) dst[i] = src[i];
}

__global__ void gather_slot_kernel(int slot) {   // -> g_xq
  int n = blockIdx.x;                 // b*LL + l
  const float* src = g_hbuf + ((size_t)n * 7 + slot) * DD;
  float* d = g_xq + (size_t)n * DD;
  for (int i = threadIdx.x; i < DD; i += blockDim.x) d[i] = src[i];
}

// ---------------- tiled SGEMM: C[M,N] = A[M,K] @ W[N,K]^T + bias ----------------
// 64x64 tile, BK=16, 256 threads, 4x4 per thread. M,K assumed multiples of 64/16
// (true for every call); N guarded (head N=50257).
__global__ __launch_bounds__(256) void gemm_bias_kernel(
    const float* __restrict__ A, const float* __restrict__ W,
    const float* __restrict__ bias, float* __restrict__ C,
    int M, int N, int K, int relu)
{
  __shared__ float As[16][64];
  __shared__ float Ws[16][64];
  int bm = blockIdx.y * 64, bn = blockIdx.x * 64;
  int tid = threadIdx.x;
  int tr = tid >> 4, tc = tid & 15;
  int lr = tid >> 2, lk = (tid & 3) << 2;
  float acc[4][4] = {{0.f}};
  const float* Ap = A + (size_t)(bm + lr) * K + lk;
  int wrow = bn + lr;
  const float* Wp = W + (size_t)wrow * K + lk;
  bool wok = wrow < N;
  for (int k0 = 0; k0 < K; k0 += 16) {
    float4 av = *(const float4*)(Ap + k0);
    float4 wv = wok ? *(const float4*)(Wp + k0) : make_float4(0.f, 0.f, 0.f, 0.f);
    As[lk    ][lr] = av.x; As[lk + 1][lr] = av.y; As[lk + 2][lr] = av.z; As[lk + 3][lr] = av.w;
    Ws[lk    ][lr] = wv.x; Ws[lk + 1][lr] = wv.y; Ws[lk + 2][lr] = wv.z; Ws[lk + 3][lr] = wv.w;
    __syncthreads();
    #pragma unroll
    for (int kk = 0; kk < 16; kk++) {
      float4 a4 = *(const float4*)&As[kk][tr << 2];
      float4 b4 = *(const float4*)&Ws[kk][tc << 2];
      float a[4] = {a4.x, a4.y, a4.z, a4.w};
      float b[4] = {b4.x, b4.y, b4.z, b4.w};
      #pragma unroll
      for (int i = 0; i < 4; i++)
        #pragma unroll
        for (int j = 0; j < 4; j++)
          acc[i][j] += a[i] * b[j];
    }
    __syncthreads();
  }
  #pragma unroll
  for (int i = 0; i < 4; i++) {
    int row = bm + (tr << 2) + i;
    #pragma unroll
    for (int j = 0; j < 4; j++) {
      int col = bn + (tc << 2) + j;
      if (col < N) {
        float v = acc[i][j] + bias[col];
        if (relu) v = fmaxf(v, 0.f);
        C[(size_t)row * N + col] = v;
      }
    }
  }
}

// ---------------- sparse-keyset attention ----------------
// One block per (b,h,l). Query row s = l*t + (t-1). Allowed keys:
//   step-0 keys j*t (j=0..L-1)  OR  same-block keys l*t + r (r=1..t-1).
// Candidates nc = L + t - 1 <= 261.
__global__ void attn_kernel(const int* __restrict__ amask, int t)
{
  int l = blockIdx.x, h = blockIdx.y, b = blockIdx.z;
  int S = LL * t;
  int nc = LL + t - 1;
  __shared__ float qs[HD];
  __shared__ float sc[LL + NSTEPS];
  __shared__ float r1[4], r2[4];
  int tid = threadIdx.x;   // 128
  if (tid < HD) qs[tid] = g_q[(size_t)(b * LL + l) * DD + h * HD + tid];
  __syncthreads();

  float lmax = -1e30f;
  for (int j = tid; j < nc; j += 128) {
    int ks  = (j < LL) ? j * t : l * t + (j - LL + 1);
    int tok = (j < LL) ? j : l;
    float sco = -1e30f;
    if (amask[b * LL + tok] != 0) {
      const float* kp = g_kv + (size_t)(b * S + ks) * (2 * DD) + h * HD;
      float d = 0.f;
      #pragma unroll
      for (int e = 0; e < HD; e++) d += qs[e] * kp[e];
      sco = d * 0.125f;   // 1/sqrt(64)
    }
    sc[j] = sco;
    lmax = fmaxf(lmax, sco);
  }
  for (int o = 16; o; o >>= 1) lmax = fmaxf(lmax, __shfl_xor_sync(0xffffffffu, lmax, o));
  if ((tid & 31) == 0) r1[tid >> 5] = lmax;
  __syncthreads();
  float m = fmaxf(fmaxf(r1[0], r1[1]), fmaxf(r1[2], r1[3]));

  float lsum = 0.f;
  for (int j = tid; j < nc; j += 128) {
    float p = __expf(sc[j] - m);
    sc[j] = p;
    lsum += p;
  }
  for (int o = 16; o; o >>= 1) lsum += __shfl_xor_sync(0xffffffffu, lsum, o);
  if ((tid & 31) == 0) r2[tid >> 5] = lsum;
  __syncthreads();
  float inv = 1.f / (r2[0] + r2[1] + r2[2] + r2[3]);

  if (tid < HD) {
    float acc = 0.f;
    for (int j = 0; j < nc; j++) {
      int ks = (j < LL) ? j * t : l * t + (j - LL + 1);
      acc += sc[j] * g_kv[(size_t)(b * S + ks) * (2 * DD) + DD + h * HD + tid];
    }
    g_attno[(size_t)(b * LL + l) * DD + h * HD + tid] = acc * inv;
  }
}

// ---------------- fused residual-add + LayerNorm ----------------
// out row: if hslot >= 0 -> g_hbuf[row*7 + hslot], else -> out + row*DD
__global__ void add_ln_kernel(const float* __restrict__ A, const float* __restrict__ R,
                              const float* __restrict__ gma, const float* __restrict__ bta,
                              float* __restrict__ out, int hslot)
{
  int row = blockIdx.x;
  int tid = threadIdx.x;   // 256, D=768 -> 3 per thread
  const float* pa = A + (size_t)row * DD;
  const float* pr = R + (size_t)row * DD;
  float* po = (hslot >= 0) ? (g_hbuf + ((size_t)row * 7 + hslot) * DD)
                           : (out + (size_t)row * DD);
  float v[3]; float s = 0.f, sq = 0.f;
  #pragma unroll
  for (int i = 0; i < 3; i++) {
    int idx = tid + i * 256;
    float xx = pa[idx] + pr[idx];
    v[i] = xx; s += xx; sq += xx * xx;
  }
  __shared__ float r1[8], r2[8];
  for (int o = 16; o; o >>= 1) {
    s  += __shfl_xor_sync(0xffffffffu, s, o);
    sq += __shfl_xor_sync(0xffffffffu, sq, o);
  }
  if ((tid & 31) == 0) { r1[tid >> 5] = s; r2[tid >> 5] = sq; }
  __syncthreads();
  s = 0.f; sq = 0.f;
  #pragma unroll
  for (int w = 0; w < 8; w++) { s += r1[w]; sq += r2[w]; }
  float mean = s * (1.f / DD);
  float var  = sq * (1.f / DD) - mean * mean;
  float rinv = rsqrtf(var + 1e-5f);
  #pragma unroll
  for (int i = 0; i < 3; i++) {
    int idx = tid + i * 256;
    po[idx] = (v[i] - mean) * rinv * gma[idx] + bta[idx];
  }
}

// ---------------- host launch ----------------
extern "C" void kernel_launch(void* const* d_in, const int* in_sizes, int n_in,
                              void* d_out, int out_size)
{
  const int*   x     = (const int*)d_in[0];
  const int*   amask = (const int*)d_in[1];
  const float* emb   = (const float*)d_in[2];
  const float* pos   = (const float*)d_in[3];
  const float* temb  = (const float*)d_in[4];
  const float* ipw   = (const float*)d_in[5];   // [2304, 768]
  const float* ipb   = (const float*)d_in[6];
  const float* aow   = (const float*)d_in[7];
  const float* aob   = (const float*)d_in[8];
  const float* ln1g  = (const float*)d_in[9];
  const float* ln1b  = (const float*)d_in[10];
  const float* w1    = (const float*)d_in[11];
  const float* b1    = (const float*)d_in[12];
  const float* w2    = (const float*)d_in[13];
  const float* b2    = (const float*)d_in[14];
  const float* ln2g  = (const float*)d_in[15];
  const float* ln2b  = (const float*)d_in[16];
  const float* hw    = (const float*)d_in[17];  // [50257, 768]
  const float* hb    = (const float*)d_in[18];
  float* out = (float*)d_out;

  float *p_xk, *p_kv, *p_xq, *p_q, *p_attno, *p_tmp, *p_y, *p_ff;
  cudaGetSymbolAddress((void**)&p_xk,    g_xk);
  cudaGetSymbolAddress((void**)&p_kv,    g_kv);
  cudaGetSymbolAddress((void**)&p_xq,    g_xq);
  cudaGetSymbolAddress((void**)&p_q,     g_q);
  cudaGetSymbolAddress((void**)&p_attno, g_attno);
  cudaGetSymbolAddress((void**)&p_tmp,   g_tmp);
  cudaGetSymbolAddress((void**)&p_y,     g_y);
  cudaGetSymbolAddress((void**)&p_ff,    g_ff);

  embed_kernel<<<NROW, 256>>>(x, emb, pos);

  dim3 grid_d((DD + 63) / 64, NROW / 64);      // 1024 x 768 GEMMs

  for (int step = 0; step < NSTEPS; step++) {
    int t = step + 1;
    int S = LL * t;
    int Nk = BB * S;

    add_time_kernel<<<NROW, 256>>>(temb, step);
    gather_xk_kernel<<<Nk, 256>>>(t);
    gather_slot_kernel<<<NROW, 256>>>(step);   // slot t-1 -> g_xq

    // K|V for all S rows: [Nk, 1536] = xk @ Wkv^T + bkv
    dim3 grid_kv((2 * DD + 63) / 64, Nk / 64);
    gemm_bias_kernel<<<grid_kv, 256>>>(p_xk, ipw + (size_t)DD * DD, ipb + DD,
                                       p_kv, Nk, 2 * DD, DD, 0);
    // Q only for query rows: [1024, 768]
    gemm_bias_kernel<<<grid_d, 256>>>(p_xq, ipw, ipb, p_q, NROW, DD, DD, 0);

    attn_kernel<<<dim3(LL, HH, BB), 128>>>(amask, t);

    // out-proj + residual + LN1
    gemm_bias_kernel<<<grid_d, 256>>>(p_attno, aow, aob, p_tmp, NROW, DD, DD, 0);
    add_ln_kernel<<<NROW, 256>>>(p_tmp, p_xq, ln1g, ln1b, p_y, -1);

    // FFN + residual + LN2 (scatter straight into hbuf slot t)
    gemm_bias_kernel<<<grid_d, 256>>>(p_y, w1, b1, p_ff, NROW, DD, DD, 1);
    gemm_bias_kernel<<<grid_d, 256>>>(p_ff, w2, b2, p_tmp, NROW, DD, DD, 0);
    add_ln_kernel<<<NROW, 256>>>(p_tmp, p_y, ln2g, ln2b, nullptr, t);
  }

  // head: logits = hbuf[:,:,6,:] @ head_w^T + head_b
  gather_slot_kernel<<<NROW, 256>>>(NSTEPS);
  dim3 grid_head((CC + 63) / 64, NROW / 64);
  gemm_bias_kernel<<<grid_head, 256>>>(p_xq, hw, hb, out, NROW, CC, DD, 0);
}

// round 2
// speedup vs baseline: 1.0033x; 1.0033x over previous
#include <cuda_runtime.h>
#include <math.h>

#define BB 4
#define LL 256
#define DD 768
#define HH 12
#define HD 64
#define NSTEPS 6
#define SMAX (LL*NSTEPS)   // 1536
#define NROW (BB*LL)       // 1024
#define CC 50257

// ---------------- scratch (device globals; no allocation) ----------------
__device__ float g_hbuf[(size_t)BB*LL*7*DD];      // [B,L,7,D] slot buffer
__device__ float g_xk  [(size_t)BB*SMAX*DD];      // keys/values input rows (contiguous)
__device__ float g_kv  [(size_t)BB*SMAX*2*DD];    // [B*S, 1536] = K|V per row
__device__ float g_xq  [(size_t)NROW*DD];         // query-row input (also head input)
__device__ float g_q   [(size_t)NROW*DD];         // projected Q
__device__ float g_attno[(size_t)NROW*DD];        // attention output (merged heads)
__device__ float g_tmp [(size_t)NROW*DD];
__device__ float g_y   [(size_t)NROW*DD];
__device__ float g_ff  [(size_t)NROW*DD];

// ---------------- small elementwise kernels ----------------
__global__ void embed_kernel(const int* __restrict__ x, const float* __restrict__ emb,
                             const float* __restrict__ pos) {
  int n = blockIdx.x;
  int l = n % LL;
  int tok = x[n];
  const float* e = emb + (size_t)tok * DD;
  const float* p = pos + (size_t)l * DD;
  float* dst = g_hbuf + (size_t)n * 7 * DD;
  for (int i = threadIdx.x; i < DD; i += blockDim.x) dst[i] = e[i] + p[i];
}

__global__ void add_time_kernel(const float* __restrict__ te, int step) {
  int n = blockIdx.x;
  float* dst = g_hbuf + ((size_t)n * 7 + step) * DD;
  const float* s = te + (size_t)step * DD;
  for (int i = threadIdx.x; i < DD; i += blockDim.x) dst[i] += s[i];
}

__global__ void gather_xk_kernel(int t) {
  int n = blockIdx.x;
  int st = LL * t;
  int b = n / st; int s = n % st; int l = s / t; int slot = s % t;
  const float* src = g_hbuf + ((size_t)(b * LL + l) * 7 + slot) * DD;
  float* dst = g_xk + (size_t)n * DD;
  for (int i = threadIdx.x; i < DD; i += blockDim.x) dst[i] = src[i];
}

__global__ void gather_slot_kernel(int slot) {
  int n = blockIdx.x;
  const float* src = g_hbuf + ((size_t)n * 7 + slot) * DD;
  float* d = g_xq + (size_t)n * DD;
  for (int i = threadIdx.x; i < DD; i += blockDim.x) d[i] = src[i];
}

// ---------------- double-buffered SGEMM: C[M,N] = A[M,K] @ W[N,K]^T + bias ----
// BMxBN tile, BK=16, 8x8 micro-tile, (BM/8)*(BN/8) threads.
// M % BM == 0, K % 16 == 0 required (true everywhere). N guarded.
template<int BM, int BN>
__global__ __launch_bounds__((BM/8)*(BN/8), 1) void gemm_dbuf_kernel(
    const float* __restrict__ A, const float* __restrict__ W,
    const float* __restrict__ bias, float* __restrict__ C,
    int M, int N, int K, int relu)
{
  constexpr int NTHR = (BM/8)*(BN/8);
  constexpr int LA = BM*16/(4*NTHR);   // float4 loads/thread for A tile
  constexpr int LW = BN*16/(4*NTHR);   // float4 loads/thread for W tile
  __shared__ float As[2][16][BM];
  __shared__ float Ws[2][16][BN];

  int bm = blockIdx.y * BM, bn = blockIdx.x * BN;
  int tid = threadIdx.x;
  int tr = tid / (BN/8);
  int tc = tid % (BN/8);

  float acc[8][8];
  #pragma unroll
  for (int i = 0; i < 8; i++)
    #pragma unroll
    for (int j = 0; j < 8; j++) acc[i][j] = 0.f;

  // ---- load tile 0 directly into smem buf 0 ----
  {
    #pragma unroll
    for (int it = 0; it < LA; it++) {
      int i = tid + it * NTHR;
      int row = i >> 2, kq = (i & 3) << 2;
      float4 v = *(const float4*)(A + (size_t)(bm + row) * K + kq);
      As[0][kq  ][row] = v.x; As[0][kq+1][row] = v.y;
      As[0][kq+2][row] = v.z; As[0][kq+3][row] = v.w;
    }
    #pragma unroll
    for (int it = 0; it < LW; it++) {
      int i = tid + it * NTHR;
      int row = i >> 2, kq = (i & 3) << 2;
      int wr = bn + row;
      float4 v = (wr < N) ? *(const float4*)(W + (size_t)wr * K + kq)
                          : make_float4(0.f, 0.f, 0.f, 0.f);
      Ws[0][kq  ][row] = v.x; Ws[0][kq+1][row] = v.y;
      Ws[0][kq+2][row] = v.z; Ws[0][kq+3][row] = v.w;
    }
  }
  __syncthreads();

  int buf = 0;
  for (int k0 = 16; k0 <= K; k0 += 16) {
    float4 pa[LA], pw[LW];
    bool more = (k0 < K);
    if (more) {
      #pragma unroll
      for (int it = 0; it < LA; it++) {
        int i = tid + it * NTHR;
        int row = i >> 2, kq = (i & 3) << 2;
        pa[it] = *(const float4*)(A + (size_t)(bm + row) * K + k0 + kq);
      }
      #pragma unroll
      for (int it = 0; it < LW; it++) {
        int i = tid + it * NTHR;
        int row = i >> 2, kq = (i & 3) << 2;
        int wr = bn + row;
        pw[it] = (wr < N) ? *(const float4*)(W + (size_t)wr * K + k0 + kq)
                          : make_float4(0.f, 0.f, 0.f, 0.f);
      }
    }
    // ---- compute current buffer ----
    #pragma unroll
    for (int kk = 0; kk < 16; kk++) {
      float4 a0 = *(const float4*)&As[buf][kk][tr*8];
      float4 a1 = *(const float4*)&As[buf][kk][tr*8+4];
      float4 w0 = *(const float4*)&Ws[buf][kk][tc*8];
      float4 w1 = *(const float4*)&Ws[buf][kk][tc*8+4];
      float a[8] = {a0.x,a0.y,a0.z,a0.w,a1.x,a1.y,a1.z,a1.w};
      float w[8] = {w0.x,w0.y,w0.z,w0.w,w1.x,w1.y,w1.z,w1.w};
      #pragma unroll
      for (int i = 0; i < 8; i++)
        #pragma unroll
        for (int j = 0; j < 8; j++)
          acc[i][j] += a[i] * w[j];
    }
    if (more) {
      int nb = buf ^ 1;
      #pragma unroll
      for (int it = 0; it < LA; it++) {
        int i = tid + it * NTHR;
        int row = i >> 2, kq = (i & 3) << 2;
        As[nb][kq  ][row] = pa[it].x; As[nb][kq+1][row] = pa[it].y;
        As[nb][kq+2][row] = pa[it].z; As[nb][kq+3][row] = pa[it].w;
      }
      #pragma unroll
      for (int it = 0; it < LW; it++) {
        int i = tid + it * NTHR;
        int row = i >> 2, kq = (i & 3) << 2;
        Ws[nb][kq  ][row] = pw[it].x; Ws[nb][kq+1][row] = pw[it].y;
        Ws[nb][kq+2][row] = pw[it].z; Ws[nb][kq+3][row] = pw[it].w;
      }
      __syncthreads();
      buf = nb;
    }
  }

  // ---- epilogue ----
  #pragma unroll
  for (int i = 0; i < 8; i++) {
    int row = bm + tr*8 + i;
    #pragma unroll
    for (int j = 0; j < 8; j++) {
      int col = bn + tc*8 + j;
      if (col < N) {
        float v = acc[i][j] + bias[col];
        if (relu) v = fmaxf(v, 0.f);
        C[(size_t)row * N + col] = v;
      }
    }
  }
}

// ---------------- sparse-keyset attention ----------------
__global__ void attn_kernel(const int* __restrict__ amask, int t)
{
  int l = blockIdx.x, h = blockIdx.y, b = blockIdx.z;
  int S = LL * t;
  int nc = LL + t - 1;
  __shared__ float qs[HD];
  __shared__ float sc[LL + NSTEPS];
  __shared__ float r1[4], r2[4];
  int tid = threadIdx.x;   // 128
  if (tid < HD) qs[tid] = g_q[(size_t)(b * LL + l) * DD + h * HD + tid];
  __syncthreads();

  float lmax = -1e30f;
  for (int j = tid; j < nc; j += 128) {
    int ks  = (j < LL) ? j * t : l * t + (j - LL + 1);
    int tok = (j < LL) ? j : l;
    float sco = -1e30f;
    if (amask[b * LL + tok] != 0) {
      const float* kp = g_kv + (size_t)(b * S + ks) * (2 * DD) + h * HD;
      float d = 0.f;
      #pragma unroll
      for (int e = 0; e < HD; e++) d += qs[e] * kp[e];
      sco = d * 0.125f;
    }
    sc[j] = sco;
    lmax = fmaxf(lmax, sco);
  }
  for (int o = 16; o; o >>= 1) lmax = fmaxf(lmax, __shfl_xor_sync(0xffffffffu, lmax, o));
  if ((tid & 31) == 0) r1[tid >> 5] = lmax;
  __syncthreads();
  float m = fmaxf(fmaxf(r1[0], r1[1]), fmaxf(r1[2], r1[3]));

  float lsum = 0.f;
  for (int j = tid; j < nc; j += 128) {
    float p = __expf(sc[j] - m);
    sc[j] = p;
    lsum += p;
  }
  for (int o = 16; o; o >>= 1) lsum += __shfl_xor_sync(0xffffffffu, lsum, o);
  if ((tid & 31) == 0) r2[tid >> 5] = lsum;
  __syncthreads();
  float inv = 1.f / (r2[0] + r2[1] + r2[2] + r2[3]);

  if (tid < HD) {
    float acc = 0.f;
    for (int j = 0; j < nc; j++) {
      int ks = (j < LL) ? j * t : l * t + (j - LL + 1);
      acc += sc[j] * g_kv[(size_t)(b * S + ks) * (2 * DD) + DD + h * HD + tid];
    }
    g_attno[(size_t)(b * LL + l) * DD + h * HD + tid] = acc * inv;
  }
}

// ---------------- fused residual-add + LayerNorm ----------------
__global__ void add_ln_kernel(const float* __restrict__ A, const float* __restrict__ R,
                              const float* __restrict__ gma, const float* __restrict__ bta,
                              float* __restrict__ out, int hslot)
{
  int row = blockIdx.x;
  int tid = threadIdx.x;   // 256
  const float* pa = A + (size_t)row * DD;
  const float* pr = R + (size_t)row * DD;
  float* po = (hslot >= 0) ? (g_hbuf + ((size_t)row * 7 + hslot) * DD)
                           : (out + (size_t)row * DD);
  float v[3]; float s = 0.f, sq = 0.f;
  #pragma unroll
  for (int i = 0; i < 3; i++) {
    int idx = tid + i * 256;
    float xx = pa[idx] + pr[idx];
    v[i] = xx; s += xx; sq += xx * xx;
  }
  __shared__ float r1[8], r2[8];
  for (int o = 16; o; o >>= 1) {
    s  += __shfl_xor_sync(0xffffffffu, s, o);
    sq += __shfl_xor_sync(0xffffffffu, sq, o);
  }
  if ((tid & 31) == 0) { r1[tid >> 5] = s; r2[tid >> 5] = sq; }
  __syncthreads();
  s = 0.f; sq = 0.f;
  #pragma unroll
  for (int w = 0; w < 8; w++) { s += r1[w]; sq += r2[w]; }
  float mean = s * (1.f / DD);
  float var  = sq * (1.f / DD) - mean * mean;
  float rinv = rsqrtf(var + 1e-5f);
  #pragma unroll
  for (int i = 0; i < 3; i++) {
    int idx = tid + i * 256;
    po[idx] = (v[i] - mean) * rinv * gma[idx] + bta[idx];
  }
}

// ---------------- host launch ----------------
extern "C" void kernel_launch(void* const* d_in, const int* in_sizes, int n_in,
                              void* d_out, int out_size)
{
  const int*   x     = (const int*)d_in[0];
  const int*   amask = (const int*)d_in[1];
  const float* emb   = (const float*)d_in[2];
  const float* pos   = (const float*)d_in[3];
  const float* temb  = (const float*)d_in[4];
  const float* ipw   = (const float*)d_in[5];
  const float* ipb   = (const float*)d_in[6];
  const float* aow   = (const float*)d_in[7];
  const float* aob   = (const float*)d_in[8];
  const float* ln1g  = (const float*)d_in[9];
  const float* ln1b  = (const float*)d_in[10];
  const float* w1    = (const float*)d_in[11];
  const float* b1    = (const float*)d_in[12];
  const float* w2    = (const float*)d_in[13];
  const float* b2    = (const float*)d_in[14];
  const float* ln2g  = (const float*)d_in[15];
  const float* ln2b  = (const float*)d_in[16];
  const float* hw    = (const float*)d_in[17];
  const float* hb    = (const float*)d_in[18];
  float* out = (float*)d_out;

  float *p_xk, *p_kv, *p_xq, *p_q, *p_attno, *p_tmp, *p_y, *p_ff;
  cudaGetSymbolAddress((void**)&p_xk,    g_xk);
  cudaGetSymbolAddress((void**)&p_kv,    g_kv);
  cudaGetSymbolAddress((void**)&p_xq,    g_xq);
  cudaGetSymbolAddress((void**)&p_q,     g_q);
  cudaGetSymbolAddress((void**)&p_attno, g_attno);
  cudaGetSymbolAddress((void**)&p_tmp,   g_tmp);
  cudaGetSymbolAddress((void**)&p_y,     g_y);
  cudaGetSymbolAddress((void**)&p_ff,    g_ff);

  embed_kernel<<<NROW, 256>>>(x, emb, pos);

  dim3 grid_sm(DD / 128, NROW / 64);   // <64,128> small per-row GEMMs: 6 x 16 = 96 blocks

  for (int step = 0; step < NSTEPS; step++) {
    int t = step + 1;
    int S = LL * t;
    int Nk = BB * S;

    add_time_kernel<<<NROW, 256>>>(temb, step);
    gather_xk_kernel<<<Nk, 256>>>(t);
    gather_slot_kernel<<<NROW, 256>>>(step);

    // K|V for all S rows: [Nk, 1536]
    dim3 grid_kv((2 * DD) / 128, Nk / 128);
    gemm_dbuf_kernel<128,128><<<grid_kv, 256>>>(p_xk, ipw + (size_t)DD * DD, ipb + DD,
                                                p_kv, Nk, 2 * DD, DD, 0);
    // Q only for query rows
    gemm_dbuf_kernel<64,128><<<grid_sm, 128>>>(p_xq, ipw, ipb, p_q, NROW, DD, DD, 0);

    attn_kernel<<<dim3(LL, HH, BB), 128>>>(amask, t);

    gemm_dbuf_kernel<64,128><<<grid_sm, 128>>>(p_attno, aow, aob, p_tmp, NROW, DD, DD, 0);
    add_ln_kernel<<<NROW, 256>>>(p_tmp, p_xq, ln1g, ln1b, p_y, -1);

    gemm_dbuf_kernel<64,128><<<grid_sm, 128>>>(p_y, w1, b1, p_ff, NROW, DD, DD, 1);
    gemm_dbuf_kernel<64,128><<<grid_sm, 128>>>(p_ff, w2, b2, p_tmp, NROW, DD, DD, 0);
    add_ln_kernel<<<NROW, 256>>>(p_tmp, p_y, ln2g, ln2b, nullptr, t);
  }

  gather_slot_kernel<<<NROW, 256>>>(NSTEPS);
  dim3 grid_head((CC + 127) / 128, NROW / 128);
  gemm_dbuf_kernel<128,128><<<grid_head, 256>>>(p_xq, hw, hb, out, NROW, CC, DD, 0);
}

// round 3
// speedup vs baseline: 1.7518x; 1.7461x over previous
#include <cuda_runtime.h>
#include <math.h>

#define BB 4
#define LL 256
#define DD 768
#define HH 12
#define HD 64
#define NSTEPS 6
#define NROW (BB*LL)       // 1024
#define CC 50257
#define KVLD (2*DD)        // 1536

// ---------------- scratch (device globals; no allocation) ----------------
__device__ float g_hbuf[(size_t)NROW*7*DD];        // [row][7 slots][D]
__device__ float g_kvc [(size_t)NROW*6*KVLD];      // [row][6 slots][K|V 1536]
__device__ float g_q   [(size_t)NROW*DD];
__device__ float g_attno[(size_t)NROW*DD];
__device__ float g_tmp [(size_t)NROW*DD];
__device__ float g_y   [(size_t)NROW*DD];
__device__ float g_ff  [(size_t)NROW*DD];

// ---------------- elementwise ----------------
__global__ void embed_kernel(const int* __restrict__ x, const float* __restrict__ emb,
                             const float* __restrict__ pos) {
  int n = blockIdx.x;
  int l = n % LL;
  int tok = x[n];
  const float* e = emb + (size_t)tok * DD;
  const float* p = pos + (size_t)l * DD;
  float* dst = g_hbuf + (size_t)n * 7 * DD;
  for (int i = threadIdx.x; i < DD; i += blockDim.x) dst[i] = e[i] + p[i];
}

__global__ void add_time_kernel(const float* __restrict__ te, int step) {
  int n = blockIdx.x;
  float* dst = g_hbuf + ((size_t)n * 7 + step) * DD;
  const float* s = te + (size_t)step * DD;
  for (int i = threadIdx.x; i < DD; i += blockDim.x) dst[i] += s[i];
}

// ---------------- double-buffered SGEMM with strides ----------------
// C[M,N] = A[M,K] @ W[N,K]^T + bias ; A row i at A+i*lda ; C row i at C+i*ldc
template<int BM, int BN>
__global__ __launch_bounds__((BM/8)*(BN/8)) void gemm_dbuf_kernel(
    const float* __restrict__ A, int lda, const float* __restrict__ W,
    const float* __restrict__ bias, float* __restrict__ C, int ldc,
    int N, int K, int relu)
{
  constexpr int NTHR = (BM/8)*(BN/8);
  constexpr int LA = BM*16/(4*NTHR);
  constexpr int LW = BN*16/(4*NTHR);
  __shared__ float As[2][16][BM];
  __shared__ float Ws[2][16][BN];

  int bm = blockIdx.y * BM, bn = blockIdx.x * BN;
  int tid = threadIdx.x;
  int tr = tid / (BN/8);
  int tc = tid % (BN/8);

  float acc[8][8];
  #pragma unroll
  for (int i = 0; i < 8; i++)
    #pragma unroll
    for (int j = 0; j < 8; j++) acc[i][j] = 0.f;

  {
    #pragma unroll
    for (int it = 0; it < LA; it++) {
      int i = tid + it * NTHR;
      int row = i >> 2, kq = (i & 3) << 2;
      float4 v = *(const float4*)(A + (size_t)(bm + row) * lda + kq);
      As[0][kq  ][row] = v.x; As[0][kq+1][row] = v.y;
      As[0][kq+2][row] = v.z; As[0][kq+3][row] = v.w;
    }
    #pragma unroll
    for (int it = 0; it < LW; it++) {
      int i = tid + it * NTHR;
      int row = i >> 2, kq = (i & 3) << 2;
      int wr = bn + row;
      float4 v = (wr < N) ? *(const float4*)(W + (size_t)wr * K + kq)
                          : make_float4(0.f, 0.f, 0.f, 0.f);
      Ws[0][kq  ][row] = v.x; Ws[0][kq+1][row] = v.y;
      Ws[0][kq+2][row] = v.z; Ws[0][kq+3][row] = v.w;
    }
  }
  __syncthreads();

  int buf = 0;
  for (int k0 = 16; k0 <= K; k0 += 16) {
    float4 pa[LA], pw[LW];
    bool more = (k0 < K);
    if (more) {
      #pragma unroll
      for (int it = 0; it < LA; it++) {
        int i = tid + it * NTHR;
        int row = i >> 2, kq = (i & 3) << 2;
        pa[it] = *(const float4*)(A + (size_t)(bm + row) * lda + k0 + kq);
      }
      #pragma unroll
      for (int it = 0; it < LW; it++) {
        int i = tid + it * NTHR;
        int row = i >> 2, kq = (i & 3) << 2;
        int wr = bn + row;
        pw[it] = (wr < N) ? *(const float4*)(W + (size_t)wr * K + k0 + kq)
                          : make_float4(0.f, 0.f, 0.f, 0.f);
      }
    }
    #pragma unroll
    for (int kk = 0; kk < 16; kk++) {
      float4 a0 = *(const float4*)&As[buf][kk][tr*8];
      float4 a1 = *(const float4*)&As[buf][kk][tr*8+4];
      float4 w0 = *(const float4*)&Ws[buf][kk][tc*8];
      float4 w1 = *(const float4*)&Ws[buf][kk][tc*8+4];
      float a[8] = {a0.x,a0.y,a0.z,a0.w,a1.x,a1.y,a1.z,a1.w};
      float w[8] = {w0.x,w0.y,w0.z,w0.w,w1.x,w1.y,w1.z,w1.w};
      #pragma unroll
      for (int i = 0; i < 8; i++)
        #pragma unroll
        for (int j = 0; j < 8; j++)
          acc[i][j] += a[i] * w[j];
    }
    if (more) {
      int nb = buf ^ 1;
      #pragma unroll
      for (int it = 0; it < LA; it++) {
        int i = tid + it * NTHR;
        int row = i >> 2, kq = (i & 3) << 2;
        As[nb][kq  ][row] = pa[it].x; As[nb][kq+1][row] = pa[it].y;
        As[nb][kq+2][row] = pa[it].z; As[nb][kq+3][row] = pa[it].w;
      }
      #pragma unroll
      for (int it = 0; it < LW; it++) {
        int i = tid + it * NTHR;
        int row = i >> 2, kq = (i & 3) << 2;
        Ws[nb][kq  ][row] = pw[it].x; Ws[nb][kq+1][row] = pw[it].y;
        Ws[nb][kq+2][row] = pw[it].z; Ws[nb][kq+3][row] = pw[it].w;
      }
      __syncthreads();
      buf = nb;
    }
  }

  #pragma unroll
  for (int i = 0; i < 8; i++) {
    int row = bm + tr*8 + i;
    #pragma unroll
    for (int j = 0; j < 8; j++) {
      int col = bn + tc*8 + j;
      if (col < N) {
        float v = acc[i][j] + bias[col];
        if (relu) v = fmaxf(v, 0.f);
        C[(size_t)row * ldc + col] = v;
      }
    }
  }
}

// ---------------- merged-head attention: one block per (b,l) ----------------
// Candidate keys j: j<LL -> (token j, slot 0) ; j>=LL -> (token l, slot j-LL+1)
#define NCMAX (LL + NSTEPS)   // 262
__global__ __launch_bounds__(256) void attn_kernel(const int* __restrict__ amask, int t)
{
  int row = blockIdx.x;          // b*LL + l
  int b = row / LL, l = row % LL;
  int nc = LL + t - 1;
  int tid = threadIdx.x, w = tid >> 5, lane = tid & 31;

  __shared__ float qs[DD];
  __shared__ float sc[NCMAX][13];     // padded: stride 13 (odd) kills conflicts
  __shared__ int   kofs[NCMAX];
  __shared__ int   mok[NCMAX];
  __shared__ float inv[HH];

  // stage q + key metadata
  #pragma unroll
  for (int i = 0; i < 3; i++) qs[tid + 256*i] = g_q[(size_t)row * DD + tid + 256*i];
  for (int j = tid; j < nc; j += 256) {
    int tok  = (j < LL) ? j : l;
    int slot = (j < LL) ? 0 : (j - LL + 1);
    kofs[j] = ((b * LL + tok) * 6 + slot) * KVLD;
    mok[j]  = amask[b * LL + tok];
  }
  __syncthreads();

  // phase 1: scores. warp per key, coalesced K loads, 12-head partial dots
  for (int j = w; j < nc; j += 8) {
    const float* kp = g_kvc + kofs[j];
    float acc[12];
    #pragma unroll
    for (int h = 0; h < 12; h++) acc[h] = 0.f;
    #pragma unroll
    for (int c = 0; c < 24; c++) {
      int e = c * 32 + lane;
      acc[c >> 1] += qs[e] * kp[e];
    }
    #pragma unroll
    for (int h = 0; h < 12; h++) {
      float v = acc[h];
      #pragma unroll
      for (int o = 16; o; o >>= 1) v += __shfl_xor_sync(0xffffffffu, v, o);
      acc[h] = v;
    }
    if (lane == 0) {
      bool ok = (mok[j] != 0);
      #pragma unroll
      for (int h = 0; h < 12; h++)
        sc[j][h] = ok ? acc[h] * 0.125f : -1e30f;
    }
  }
  __syncthreads();

  // phase 2: per-head softmax (warp per head)
  for (int h = w; h < HH; h += 8) {
    float m = -1e30f;
    for (int j = lane; j < nc; j += 32) m = fmaxf(m, sc[j][h]);
    #pragma unroll
    for (int o = 16; o; o >>= 1) m = fmaxf(m, __shfl_xor_sync(0xffffffffu, m, o));
    float s = 0.f;
    for (int j = lane; j < nc; j += 32) {
      float p = __expf(sc[j][h] - m);
      sc[j][h] = p;
      s += p;
    }
    #pragma unroll
    for (int o = 16; o; o >>= 1) s += __shfl_xor_sync(0xffffffffu, s, o);
    if (lane == 0) inv[h] = 1.f / s;
  }
  __syncthreads();

  // phase 3: output. thread owns elements e = tid + 256*i ; coalesced V loads
  #pragma unroll
  for (int i = 0; i < 3; i++) {
    int e = tid + 256 * i;
    int h = e >> 6;
    float o = 0.f;
    for (int j = 0; j < nc; j++)
      o += sc[j][h] * g_kvc[kofs[j] + DD + e];
    g_attno[(size_t)row * DD + e] = o * inv[h];
  }
}

// ---------------- fused residual-add + LayerNorm (strided) ----------------
__global__ void add_ln_kernel(const float* __restrict__ A, int lda,
                              const float* __restrict__ R, int ldr,
                              const float* __restrict__ gma, const float* __restrict__ bta,
                              float* __restrict__ out, int ldo)
{
  int row = blockIdx.x;
  int tid = threadIdx.x;   // 256
  const float* pa = A + (size_t)row * lda;
  const float* pr = R + (size_t)row * ldr;
  float* po = out + (size_t)row * ldo;
  float v[3]; float s = 0.f, sq = 0.f;
  #pragma unroll
  for (int i = 0; i < 3; i++) {
    int idx = tid + i * 256;
    float xx = pa[idx] + pr[idx];
    v[i] = xx; s += xx; sq += xx * xx;
  }
  __shared__ float r1[8], r2[8];
  for (int o = 16; o; o >>= 1) {
    s  += __shfl_xor_sync(0xffffffffu, s, o);
    sq += __shfl_xor_sync(0xffffffffu, sq, o);
  }
  if ((tid & 31) == 0) { r1[tid >> 5] = s; r2[tid >> 5] = sq; }
  __syncthreads();
  s = 0.f; sq = 0.f;
  #pragma unroll
  for (int ww = 0; ww < 8; ww++) { s += r1[ww]; sq += r2[ww]; }
  float mean = s * (1.f / DD);
  float var  = sq * (1.f / DD) - mean * mean;
  float rinv = rsqrtf(var + 1e-5f);
  #pragma unroll
  for (int i = 0; i < 3; i++) {
    int idx = tid + i * 256;
    po[idx] = (v[i] - mean) * rinv * gma[idx] + bta[idx];
  }
}

// ---------------- host launch ----------------
extern "C" void kernel_launch(void* const* d_in, const int* in_sizes, int n_in,
                              void* d_out, int out_size)
{
  const int*   x     = (const int*)d_in[0];
  const int*   amask = (const int*)d_in[1];
  const float* emb   = (const float*)d_in[2];
  const float* pos   = (const float*)d_in[3];
  const float* temb  = (const float*)d_in[4];
  const float* ipw   = (const float*)d_in[5];
  const float* ipb   = (const float*)d_in[6];
  const float* aow   = (const float*)d_in[7];
  const float* aob   = (const float*)d_in[8];
  const float* ln1g  = (const float*)d_in[9];
  const float* ln1b  = (const float*)d_in[10];
  const float* w1    = (const float*)d_in[11];
  const float* b1    = (const float*)d_in[12];
  const float* w2    = (const float*)d_in[13];
  const float* b2    = (const float*)d_in[14];
  const float* ln2g  = (const float*)d_in[15];
  const float* ln2b  = (const float*)d_in[16];
  const float* hw    = (const float*)d_in[17];
  const float* hb    = (const float*)d_in[18];
  float* out = (float*)d_out;

  float *p_hbuf, *p_kvc, *p_q, *p_attno, *p_tmp, *p_y, *p_ff;
  cudaGetSymbolAddress((void**)&p_hbuf,  g_hbuf);
  cudaGetSymbolAddress((void**)&p_kvc,   g_kvc);
  cudaGetSymbolAddress((void**)&p_q,     g_q);
  cudaGetSymbolAddress((void**)&p_attno, g_attno);
  cudaGetSymbolAddress((void**)&p_tmp,   g_tmp);
  cudaGetSymbolAddress((void**)&p_y,     g_y);
  cudaGetSymbolAddress((void**)&p_ff,    g_ff);

  embed_kernel<<<NROW, 256>>>(x, emb, pos);

  dim3 grid_sm(DD / 128, NROW / 64);       // <64,128>: 6 x 16 = 96 blocks
  dim3 grid_kv(KVLD / 128, NROW / 128);    // <128,128>: 12 x 8 = 96 blocks

  for (int step = 0; step < NSTEPS; step++) {
    // add time emb to newest slot (= step)
    add_time_kernel<<<NROW, 256>>>(temb, step);

    const float* slotA = p_hbuf + (size_t)step * DD;   // lda = 7*DD

    // incremental K|V for the new slot only: 1024 x 1536 x 768
    gemm_dbuf_kernel<128,128><<<grid_kv, 256>>>(slotA, 7*DD, ipw + (size_t)DD*DD,
                                                ipb + DD, p_kvc + (size_t)step*KVLD,
                                                6*KVLD, KVLD, DD, 0);
    // Q for query rows (same slot)
    gemm_dbuf_kernel<64,128><<<grid_sm, 128>>>(slotA, 7*DD, ipw, ipb,
                                               p_q, DD, DD, DD, 0);

    attn_kernel<<<NROW, 256>>>(amask, step + 1);

    gemm_dbuf_kernel<64,128><<<grid_sm, 128>>>(p_attno, DD, aow, aob,
                                               p_tmp, DD, DD, DD, 0);
    add_ln_kernel<<<NROW, 256>>>(p_tmp, DD, slotA, 7*DD, ln1g, ln1b, p_y, DD);

    gemm_dbuf_kernel<64,128><<<grid_sm, 128>>>(p_y, DD, w1, b1, p_ff, DD, DD, DD, 1);
    gemm_dbuf_kernel<64,128><<<grid_sm, 128>>>(p_ff, DD, w2, b2, p_tmp, DD, DD, DD, 0);
    add_ln_kernel<<<NROW, 256>>>(p_tmp, DD, p_y, DD, ln2g, ln2b,
                                 p_hbuf + (size_t)(step + 1) * DD, 7*DD);
  }

  // head: logits = hbuf slot 6 @ head_w^T + head_b
  dim3 grid_head((CC + 127) / 128, NROW / 128);
  gemm_dbuf_kernel<128,128><<<grid_head, 256>>>(p_hbuf + (size_t)6*DD, 7*DD, hw, hb,
                                                out, CC, CC, DD, 0);
}

// round 5
// speedup vs baseline: 3.5753x; 2.0409x over previous
#include <cuda_runtime.h>
#include <cuda_bf16.h>
#include <math.h>
#include <stdint.h>

#define BB 4
#define LL 256
#define DD 768
#define HH 12
#define NSTEPS 6
#define NROW 1024
#define CC 50257
#define QKVLD 2304
#define KDIM 768

// ---------------- scratch (device globals; no allocation) ----------------
__device__ float g_hbuf[(size_t)NROW*7*DD];        // [row][7 slots][D]
__device__ float g_qkvc[(size_t)NROW*6*QKVLD];     // [row][6 slots][Q|K|V]
__device__ float g_attno[(size_t)NROW*DD];
__device__ float g_tmp [(size_t)NROW*DD];
__device__ float g_y   [(size_t)NROW*DD];
__device__ float g_ff  [(size_t)NROW*DD];

// ---------------- helpers ----------------
__device__ __forceinline__ uint32_t s2u(const void* p){
  uint32_t a; asm("{ .reg .u64 t; cvta.to.shared.u64 t, %1; cvt.u32.u64 %0, t; }"
                  : "=r"(a) : "l"(p)); return a;
}
__device__ __forceinline__ void ldsm4(uint32_t* r, uint32_t addr){
  asm volatile("ldmatrix.sync.aligned.m8n8.x4.shared.b16 {%0,%1,%2,%3}, [%4];"
    : "=r"(r[0]),"=r"(r[1]),"=r"(r[2]),"=r"(r[3]) : "r"(addr));
}
__device__ __forceinline__ void mma16816(float* c, const uint32_t* a, const uint32_t* b){
  asm volatile("mma.sync.aligned.m16n8k16.row.col.f32.bf16.bf16.f32 "
    "{%0,%1,%2,%3}, {%4,%5,%6,%7}, {%8,%9}, {%0,%1,%2,%3};"
    : "+f"(c[0]),"+f"(c[1]),"+f"(c[2]),"+f"(c[3])
    : "r"(a[0]),"r"(a[1]),"r"(a[2]),"r"(a[3]), "r"(b[0]),"r"(b[1]));
}
// split two fp32 into packed bf16 hi-pair and lo-pair (low half = first elem)
__device__ __forceinline__ void split2(float a, float b, uint32_t& h, uint32_t& l){
  __nv_bfloat16 ha = __float2bfloat16(a), hb = __float2bfloat16(b);
  __nv_bfloat16 la = __float2bfloat16(a - __bfloat162float(ha));
  __nv_bfloat16 lb = __float2bfloat16(b - __bfloat162float(hb));
  uint16_t uha = *(uint16_t*)&ha, uhb = *(uint16_t*)&hb;
  uint16_t ula = *(uint16_t*)&la, ulb = *(uint16_t*)&lb;
  h = ((uint32_t)uhb << 16) | uha;
  l = ((uint32_t)ulb << 16) | ula;
}

// ---------------- elementwise ----------------
__global__ void embed_kernel(const int* __restrict__ x, const float* __restrict__ emb,
                             const float* __restrict__ pos) {
  int n = blockIdx.x;
  int l = n % LL;
  int tok = x[n];
  const float* e = emb + (size_t)tok * DD;
  const float* p = pos + (size_t)l * DD;
  float* dst = g_hbuf + (size_t)n * 7 * DD;
  for (int i = threadIdx.x; i < DD; i += blockDim.x) dst[i] = e[i] + p[i];
}

__global__ void add_time_kernel(const float* __restrict__ te, int step) {
  int n = blockIdx.x;
  float* dst = g_hbuf + ((size_t)n * 7 + step) * DD;
  const float* s = te + (size_t)step * DD;
  for (int i = threadIdx.x; i < DD; i += blockDim.x) dst[i] += s[i];
}

// ---------------- mma.sync bf16-split GEMM ----------------
// C[M,N] = A[M,K=768] @ W[N,768]^T + bias  (fp32 in/out, 3-term bf16 split)
// BMxBN tile, BK=32, warp tile 64x32. grid.x = M tiles, grid.y = N tiles.
template<int BM, int BN>
__global__ __launch_bounds__((BM/64)*(BN/32)*32)
void gemm_mma_kernel(const float* __restrict__ A, int lda,
                     const float* __restrict__ W,
                     const float* __restrict__ bias,
                     float* __restrict__ C, int ldc, int N, int relu)
{
  constexpr int NWN = BN/32;
  constexpr int NTHR = (BM/64)*(BN/32)*32;
  constexpr int RPP = NTHR/8;          // rows loaded per pass (8 thr/row: 32 k / float4)
  constexpr int PA = BM/RPP, PB = BN/RPP;
  constexpr int ABYTES = BM*64, BBYTES = BN*64;   // row = 32 bf16 = 64B
  constexpr int NIT = KDIM/32;         // 24

  extern __shared__ char smem[];
  const int OAh = 0, OAl = 2*ABYTES, OBh = 4*ABYTES, OBl = 4*ABYTES + 2*BBYTES;
  uint32_t sb = s2u(smem);

  int tid = threadIdx.x, lane = tid & 31, wid = tid >> 5;
  int wm = wid / NWN, wn = wid % NWN;
  int bm = blockIdx.x * BM, bn = blockIdx.y * BN;
  int lr = tid >> 3, lq = tid & 7;

  float acc[4][4][4];
  #pragma unroll
  for (int i = 0; i < 4; i++)
    #pragma unroll
    for (int j = 0; j < 4; j++)
      #pragma unroll
      for (int q = 0; q < 4; q++) acc[i][j][q] = 0.f;

  float4 sa[PA], swt[PB];

  auto load_tiles = [&](int k0){
    #pragma unroll
    for (int p = 0; p < PA; p++)
      sa[p] = *(const float4*)(A + (size_t)(bm + p*RPP + lr) * lda + k0 + lq*4);
    #pragma unroll
    for (int p = 0; p < PB; p++) {
      int wr = bn + p*RPP + lr;
      swt[p] = (wr < N) ? *(const float4*)(W + (size_t)wr * KDIM + k0 + lq*4)
                        : make_float4(0.f,0.f,0.f,0.f);
    }
  };
  auto store_tiles = [&](int b){
    #pragma unroll
    for (int p = 0; p < PA; p++) {
      int r = p*RPP + lr;
      int byte = r*64 + ((((lq>>1) ^ ((r>>1)&3))<<4) | ((lq&1)<<3));
      uint32_t h0,l0,h1,l1;
      split2(sa[p].x, sa[p].y, h0, l0);
      split2(sa[p].z, sa[p].w, h1, l1);
      *(uint2*)(smem + OAh + b*ABYTES + byte) = make_uint2(h0,h1);
      *(uint2*)(smem + OAl + b*ABYTES + byte) = make_uint2(l0,l1);
    }
    #pragma unroll
    for (int p = 0; p < PB; p++) {
      int r = p*RPP + lr;
      int byte = r*64 + ((((lq>>1) ^ ((r>>1)&3))<<4) | ((lq&1)<<3));
      uint32_t h0,l0,h1,l1;
      split2(swt[p].x, swt[p].y, h0, l0);
      split2(swt[p].z, swt[p].w, h1, l1);
      *(uint2*)(smem + OBh + b*BBYTES + byte) = make_uint2(h0,h1);
      *(uint2*)(smem + OBl + b*BBYTES + byte) = make_uint2(l0,l1);
    }
  };

  load_tiles(0);
  store_tiles(0);
  __syncthreads();

  int buf = 0;
  for (int it = 0; it < NIT; it++) {
    bool more = (it < NIT-1);
    if (more) load_tiles((it+1)*32);

    #pragma unroll
    for (int ks = 0; ks < 2; ks++) {
      uint32_t ah[4][4], al[4][4], bh[4][2], bl[4][2];
      #pragma unroll
      for (int mi = 0; mi < 4; mi++) {
        int r = wm*64 + mi*16 + (lane & 15);
        int kc = ks*2 + (lane >> 4);
        uint32_t byte = r*64 + ((kc ^ ((r>>1)&3))<<4);
        ldsm4(ah[mi], sb + OAh + buf*ABYTES + byte);
        ldsm4(al[mi], sb + OAl + buf*ABYTES + byte);
      }
      #pragma unroll
      for (int np = 0; np < 2; np++) {
        int r = wn*32 + np*16 + (lane & 7) + ((lane>>4)&1)*8;
        int kc = ks*2 + ((lane>>3)&1);
        uint32_t byte = r*64 + ((kc ^ ((r>>1)&3))<<4);
        uint32_t t4[4];
        ldsm4(t4, sb + OBh + buf*BBYTES + byte);
        bh[np*2][0]=t4[0]; bh[np*2][1]=t4[1]; bh[np*2+1][0]=t4[2]; bh[np*2+1][1]=t4[3];
        ldsm4(t4, sb + OBl + buf*BBYTES + byte);
        bl[np*2][0]=t4[0]; bl[np*2][1]=t4[1]; bl[np*2+1][0]=t4[2]; bl[np*2+1][1]=t4[3];
      }
      #pragma unroll
      for (int mi = 0; mi < 4; mi++)
        #pragma unroll
        for (int ni = 0; ni < 4; ni++) {
          mma16816(acc[mi][ni], ah[mi], bh[ni]);
          mma16816(acc[mi][ni], ah[mi], bl[ni]);
          mma16816(acc[mi][ni], al[mi], bh[ni]);
        }
    }
    if (more) {
      store_tiles(buf ^ 1);
      __syncthreads();
      buf ^= 1;
    }
  }

  // epilogue
  #pragma unroll
  for (int mi = 0; mi < 4; mi++) {
    int r0 = bm + wm*64 + mi*16 + (lane >> 2);
    #pragma unroll
    for (int ni = 0; ni < 4; ni++) {
      int c0 = bn + wn*32 + ni*8 + ((lane & 3) << 1);
      float* p0 = C + (size_t)r0 * ldc;
      float* p1 = C + (size_t)(r0 + 8) * ldc;
      if (c0 < N) {
        float bv = __ldg(bias + c0);
        float v0 = acc[mi][ni][0] + bv;
        float v2 = acc[mi][ni][2] + bv;
        if (relu) { v0 = fmaxf(v0, 0.f); v2 = fmaxf(v2, 0.f); }
        p0[c0] = v0; p1[c0] = v2;
      }
      if (c0 + 1 < N) {
        float bv = __ldg(bias + c0 + 1);
        float v1 = acc[mi][ni][1] + bv;
        float v3 = acc[mi][ni][3] + bv;
        if (relu) { v1 = fmaxf(v1, 0.f); v3 = fmaxf(v3, 0.f); }
        p0[c0+1] = v1; p1[c0+1] = v3;
      }
    }
  }
}

// ---------------- merged-head attention over QKV cache ----------------
#define NCMAX (LL + NSTEPS)
__global__ __launch_bounds__(256) void attn_kernel(const int* __restrict__ amask, int t)
{
  int row = blockIdx.x;
  int b = row / LL, l = row % LL;
  int nc = LL + t - 1;
  int tid = threadIdx.x, w = tid >> 5, lane = tid & 31;

  __shared__ float qs[DD];
  __shared__ float sc[NCMAX][13];
  __shared__ int   kofs[NCMAX];
  __shared__ int   mok[NCMAX];
  __shared__ float inv[HH];

  int qoff = (row * 6 + (t - 1)) * QKVLD;
  #pragma unroll
  for (int i = 0; i < 3; i++) qs[tid + 256*i] = g_qkvc[qoff + tid + 256*i];
  for (int j = tid; j < nc; j += 256) {
    int tok  = (j < LL) ? j : l;
    int slot = (j < LL) ? 0 : (j - LL + 1);
    kofs[j] = ((b * LL + tok) * 6 + slot) * QKVLD;
    mok[j]  = amask[b * LL + tok];
  }
  __syncthreads();

  for (int j = w; j < nc; j += 8) {
    const float* kp = g_qkvc + kofs[j] + DD;
    float acc[12];
    #pragma unroll
    for (int h = 0; h < 12; h++) acc[h] = 0.f;
    #pragma unroll
    for (int c = 0; c < 24; c++) {
      int e = c * 32 + lane;
      acc[c >> 1] += qs[e] * kp[e];
    }
    #pragma unroll
    for (int h = 0; h < 12; h++) {
      float v = acc[h];
      #pragma unroll
      for (int o = 16; o; o >>= 1) v += __shfl_xor_sync(0xffffffffu, v, o);
      acc[h] = v;
    }
    if (lane == 0) {
      bool ok = (mok[j] != 0);
      #pragma unroll
      for (int h = 0; h < 12; h++)
        sc[j][h] = ok ? acc[h] * 0.125f : -1e30f;
    }
  }
  __syncthreads();

  for (int h = w; h < HH; h += 8) {
    float m = -1e30f;
    for (int j = lane; j < nc; j += 32) m = fmaxf(m, sc[j][h]);
    #pragma unroll
    for (int o = 16; o; o >>= 1) m = fmaxf(m, __shfl_xor_sync(0xffffffffu, m, o));
    float s = 0.f;
    for (int j = lane; j < nc; j += 32) {
      float p = __expf(sc[j][h] - m);
      sc[j][h] = p;
      s += p;
    }
    #pragma unroll
    for (int o = 16; o; o >>= 1) s += __shfl_xor_sync(0xffffffffu, s, o);
    if (lane == 0) inv[h] = 1.f / s;
  }
  __syncthreads();

  #pragma unroll
  for (int i = 0; i < 3; i++) {
    int e = tid + 256 * i;
    int h = e >> 6;
    float o = 0.f;
    for (int j = 0; j < nc; j++)
      o += sc[j][h] * g_qkvc[kofs[j] + 2*DD + e];
    g_attno[(size_t)row * DD + e] = o * inv[h];
  }
}

// ---------------- fused residual-add + LayerNorm (strided) ----------------
__global__ void add_ln_kernel(const float* __restrict__ A, int lda,
                              const float* __restrict__ R, int ldr,
                              const float* __restrict__ gma, const float* __restrict__ bta,
                              float* __restrict__ out, int ldo)
{
  int row = blockIdx.x;
  int tid = threadIdx.x;
  const float* pa = A + (size_t)row * lda;
  const float* pr = R + (size_t)row * ldr;
  float* po = out + (size_t)row * ldo;
  float v[3]; float s = 0.f, sq = 0.f;
  #pragma unroll
  for (int i = 0; i < 3; i++) {
    int idx = tid + i * 256;
    float xx = pa[idx] + pr[idx];
    v[i] = xx; s += xx; sq += xx * xx;
  }
  __shared__ float r1[8], r2[8];
  for (int o = 16; o; o >>= 1) {
    s  += __shfl_xor_sync(0xffffffffu, s, o);
    sq += __shfl_xor_sync(0xffffffffu, sq, o);
  }
  if ((tid & 31) == 0) { r1[tid >> 5] = s; r2[tid >> 5] = sq; }
  __syncthreads();
  s = 0.f; sq = 0.f;
  #pragma unroll
  for (int ww = 0; ww < 8; ww++) { s += r1[ww]; sq += r2[ww]; }
  float mean = s * (1.f / DD);
  float var  = sq * (1.f / DD) - mean * mean;
  float rinv = rsqrtf(var + 1e-5f);
  #pragma unroll
  for (int i = 0; i < 3; i++) {
    int idx = tid + i * 256;
    po[idx] = (v[i] - mean) * rinv * gma[idx] + bta[idx];
  }
}

// ---------------- host launch ----------------
extern "C" void kernel_launch(void* const* d_in, const int* in_sizes, int n_in,
                              void* d_out, int out_size)
{
  const int*   x     = (const int*)d_in[0];
  const int*   amask = (const int*)d_in[1];
  const float* emb   = (const float*)d_in[2];
  const float* pos   = (const float*)d_in[3];
  const float* temb  = (const float*)d_in[4];
  const float* ipw   = (const float*)d_in[5];
  const float* ipb   = (const float*)d_in[6];
  const float* aow   = (const float*)d_in[7];
  const float* aob   = (const float*)d_in[8];
  const float* ln1g  = (const float*)d_in[9];
  const float* ln1b  = (const float*)d_in[10];
  const float* w1    = (const float*)d_in[11];
  const float* b1    = (const float*)d_in[12];
  const float* w2    = (const float*)d_in[13];
  const float* b2    = (const float*)d_in[14];
  const float* ln2g  = (const float*)d_in[15];
  const float* ln2b  = (const float*)d_in[16];
  const float* hw    = (const float*)d_in[17];
  const float* hb    = (const float*)d_in[18];
  float* out = (float*)d_out;

  float *p_hbuf, *p_qkvc, *p_attno, *p_tmp, *p_y, *p_ff;
  cudaGetSymbolAddress((void**)&p_hbuf,  g_hbuf);
  cudaGetSymbolAddress((void**)&p_qkvc,  g_qkvc);
  cudaGetSymbolAddress((void**)&p_attno, g_attno);
  cudaGetSymbolAddress((void**)&p_tmp,   g_tmp);
  cudaGetSymbolAddress((void**)&p_y,     g_y);
  cudaGetSymbolAddress((void**)&p_ff,    g_ff);

  const int SM_BIG = (128+128)*256;   // 64KB
  const int SM_SML = (64+128)*256;    // 48KB
  cudaFuncSetAttribute(gemm_mma_kernel<128,128>,
                       cudaFuncAttributeMaxDynamicSharedMemorySize, SM_BIG);
  cudaFuncSetAttribute(gemm_mma_kernel<64,128>,
                       cudaFuncAttributeMaxDynamicSharedMemorySize, SM_SML);

  embed_kernel<<<NROW, 256>>>(x, emb, pos);

  dim3 grid_sm(NROW/64, DD/128);     // <64,128>: 16 x 6
  dim3 grid_qkv(NROW/128, QKVLD/128);// <128,128>: 8 x 18

  for (int step = 0; step < NSTEPS; step++) {
    add_time_kernel<<<NROW, 256>>>(temb, step);

    const float* slotA = p_hbuf + (size_t)step * DD;

    gemm_mma_kernel<128,128><<<grid_qkv, 256, SM_BIG>>>(
        slotA, 7*DD, ipw, ipb, p_qkvc + (size_t)step*QKVLD, 6*QKVLD, QKVLD, 0);

    attn_kernel<<<NROW, 256>>>(amask, step + 1);

    gemm_mma_kernel<64,128><<<grid_sm, 128, SM_SML>>>(
        p_attno, DD, aow, aob, p_tmp, DD, DD, 0);
    add_ln_kernel<<<NROW, 256>>>(p_tmp, DD, slotA, 7*DD, ln1g, ln1b, p_y, DD);

    gemm_mma_kernel<64,128><<<grid_sm, 128, SM_SML>>>(
        p_y, DD, w1, b1, p_ff, DD, DD, 1);
    gemm_mma_kernel<64,128><<<grid_sm, 128, SM_SML>>>(
        p_ff, DD, w2, b2, p_tmp, DD, DD, 0);
    add_ln_kernel<<<NROW, 256>>>(p_tmp, DD, p_y, DD, ln2g, ln2b,
                                 p_hbuf + (size_t)(step + 1) * DD, 7*DD);
  }

  dim3 grid_head(NROW/128, (CC + 127)/128);   // 8 x 393
  gemm_mma_kernel<128,128><<<grid_head, 256, SM_BIG>>>(
      p_hbuf + (size_t)6*DD, 7*DD, hw, hb, out, CC, CC, 0);
}

// round 6
// speedup vs baseline: 4.6090x; 1.2891x over previous
#include <cuda_runtime.h>
#include <cuda_bf16.h>
#include <math.h>
#include <stdint.h>

#define BB 4
#define LL 256
#define DD 768
#define HH 12
#define NSTEPS 6
#define NROW 1024
#define CC 50257
#define QKVLD 2304
#define KDIM 768

// ---------------- scratch (device globals; no allocation) ----------------
__device__ float g_hbuf[(size_t)NROW*7*DD];        // [row][7 slots][D]
__device__ float g_qkvc[(size_t)NROW*6*QKVLD];     // [row][6 slots][Q|K|V]
__device__ float g_attno[(size_t)NROW*DD];
__device__ float g_tmp [(size_t)NROW*DD];
__device__ float g_y   [(size_t)NROW*DD];
__device__ float g_ff  [(size_t)NROW*DD];

// ---------------- helpers ----------------
__device__ __forceinline__ uint32_t s2u(const void* p){
  uint32_t a; asm("{ .reg .u64 t; cvta.to.shared.u64 t, %1; cvt.u32.u64 %0, t; }"
                  : "=r"(a) : "l"(p)); return a;
}
__device__ __forceinline__ void ldsm4(uint32_t* r, uint32_t addr){
  asm volatile("ldmatrix.sync.aligned.m8n8.x4.shared.b16 {%0,%1,%2,%3}, [%4];"
    : "=r"(r[0]),"=r"(r[1]),"=r"(r[2]),"=r"(r[3]) : "r"(addr));
}
__device__ __forceinline__ void mma16816(float* c, const uint32_t* a, const uint32_t* b){
  asm volatile("mma.sync.aligned.m16n8k16.row.col.f32.bf16.bf16.f32 "
    "{%0,%1,%2,%3}, {%4,%5,%6,%7}, {%8,%9}, {%0,%1,%2,%3};"
    : "+f"(c[0]),"+f"(c[1]),"+f"(c[2]),"+f"(c[3])
    : "r"(a[0]),"r"(a[1]),"r"(a[2]),"r"(a[3]), "r"(b[0]),"r"(b[1]));
}
__device__ __forceinline__ void split2(float a, float b, uint32_t& h, uint32_t& l){
  __nv_bfloat16 ha = __float2bfloat16(a), hb = __float2bfloat16(b);
  __nv_bfloat16 la = __float2bfloat16(a - __bfloat162float(ha));
  __nv_bfloat16 lb = __float2bfloat16(b - __bfloat162float(hb));
  uint16_t uha = *(uint16_t*)&ha, uhb = *(uint16_t*)&hb;
  uint16_t ula = *(uint16_t*)&la, ulb = *(uint16_t*)&lb;
  h = ((uint32_t)uhb << 16) | uha;
  l = ((uint32_t)ulb << 16) | ula;
}

// ---------------- elementwise ----------------
__global__ void embed_kernel(const int* __restrict__ x, const float* __restrict__ emb,
                             const float* __restrict__ pos) {
  int n = blockIdx.x;
  int l = n % LL;
  int tok = x[n];
  const float* e = emb + (size_t)tok * DD;
  const float* p = pos + (size_t)l * DD;
  float* dst = g_hbuf + (size_t)n * 7 * DD;
  for (int i = threadIdx.x; i < DD; i += blockDim.x) dst[i] = e[i] + p[i];
}

__global__ void add_time_kernel(const float* __restrict__ te, int step) {
  int n = blockIdx.x;
  float* dst = g_hbuf + ((size_t)n * 7 + step) * DD;
  const float* s = te + (size_t)step * DD;
  for (int i = threadIdx.x; i < DD; i += blockDim.x) dst[i] += s[i];
}

// ---------------- mma.sync bf16-split GEMM ----------------
template<int BM, int BN>
__global__ __launch_bounds__((BM/64)*(BN/32)*32)
void gemm_mma_kernel(const float* __restrict__ A, int lda,
                     const float* __restrict__ W,
                     const float* __restrict__ bias,
                     float* __restrict__ C, int ldc, int N, int relu)
{
  constexpr int NWN = BN/32;
  constexpr int NTHR = (BM/64)*(BN/32)*32;
  constexpr int RPP = NTHR/8;
  constexpr int PA = BM/RPP, PB = BN/RPP;
  constexpr int ABYTES = BM*64, BBYTES = BN*64;
  constexpr int NIT = KDIM/32;

  extern __shared__ char smem[];
  const int OAh = 0, OAl = 2*ABYTES, OBh = 4*ABYTES, OBl = 4*ABYTES + 2*BBYTES;
  uint32_t sb = s2u(smem);

  int tid = threadIdx.x, lane = tid & 31, wid = tid >> 5;
  int wm = wid / NWN, wn = wid % NWN;
  int bm = blockIdx.x * BM, bn = blockIdx.y * BN;
  int lr = tid >> 3, lq = tid & 7;

  float acc[4][4][4];
  #pragma unroll
  for (int i = 0; i < 4; i++)
    #pragma unroll
    for (int j = 0; j < 4; j++)
      #pragma unroll
      for (int q = 0; q < 4; q++) acc[i][j][q] = 0.f;

  float4 sa[PA], swt[PB];

  auto load_tiles = [&](int k0){
    #pragma unroll
    for (int p = 0; p < PA; p++)
      sa[p] = *(const float4*)(A + (size_t)(bm + p*RPP + lr) * lda + k0 + lq*4);
    #pragma unroll
    for (int p = 0; p < PB; p++) {
      int wr = bn + p*RPP + lr;
      swt[p] = (wr < N) ? *(const float4*)(W + (size_t)wr * KDIM + k0 + lq*4)
                        : make_float4(0.f,0.f,0.f,0.f);
    }
  };
  auto store_tiles = [&](int b){
    #pragma unroll
    for (int p = 0; p < PA; p++) {
      int r = p*RPP + lr;
      int byte = r*64 + ((((lq>>1) ^ ((r>>1)&3))<<4) | ((lq&1)<<3));
      uint32_t h0,l0,h1,l1;
      split2(sa[p].x, sa[p].y, h0, l0);
      split2(sa[p].z, sa[p].w, h1, l1);
      *(uint2*)(smem + OAh + b*ABYTES + byte) = make_uint2(h0,h1);
      *(uint2*)(smem + OAl + b*ABYTES + byte) = make_uint2(l0,l1);
    }
    #pragma unroll
    for (int p = 0; p < PB; p++) {
      int r = p*RPP + lr;
      int byte = r*64 + ((((lq>>1) ^ ((r>>1)&3))<<4) | ((lq&1)<<3));
      uint32_t h0,l0,h1,l1;
      split2(swt[p].x, swt[p].y, h0, l0);
      split2(swt[p].z, swt[p].w, h1, l1);
      *(uint2*)(smem + OBh + b*BBYTES + byte) = make_uint2(h0,h1);
      *(uint2*)(smem + OBl + b*BBYTES + byte) = make_uint2(l0,l1);
    }
  };

  load_tiles(0);
  store_tiles(0);
  __syncthreads();

  int buf = 0;
  for (int it = 0; it < NIT; it++) {
    bool more = (it < NIT-1);
    if (more) load_tiles((it+1)*32);

    #pragma unroll
    for (int ks = 0; ks < 2; ks++) {
      uint32_t ah[4][4], al[4][4], bh[4][2], bl[4][2];
      #pragma unroll
      for (int mi = 0; mi < 4; mi++) {
        int r = wm*64 + mi*16 + (lane & 15);
        int kc = ks*2 + (lane >> 4);
        uint32_t byte = r*64 + ((kc ^ ((r>>1)&3))<<4);
        ldsm4(ah[mi], sb + OAh + buf*ABYTES + byte);
        ldsm4(al[mi], sb + OAl + buf*ABYTES + byte);
      }
      #pragma unroll
      for (int np = 0; np < 2; np++) {
        int r = wn*32 + np*16 + (lane & 7) + ((lane>>4)&1)*8;
        int kc = ks*2 + ((lane>>3)&1);
        uint32_t byte = r*64 + ((kc ^ ((r>>1)&3))<<4);
        uint32_t t4[4];
        ldsm4(t4, sb + OBh + buf*BBYTES + byte);
        bh[np*2][0]=t4[0]; bh[np*2][1]=t4[1]; bh[np*2+1][0]=t4[2]; bh[np*2+1][1]=t4[3];
        ldsm4(t4, sb + OBl + buf*BBYTES + byte);
        bl[np*2][0]=t4[0]; bl[np*2][1]=t4[1]; bl[np*2+1][0]=t4[2]; bl[np*2+1][1]=t4[3];
      }
      #pragma unroll
      for (int mi = 0; mi < 4; mi++)
        #pragma unroll
        for (int ni = 0; ni < 4; ni++) {
          mma16816(acc[mi][ni], ah[mi], bh[ni]);
          mma16816(acc[mi][ni], ah[mi], bl[ni]);
          mma16816(acc[mi][ni], al[mi], bh[ni]);
        }
    }
    if (more) {
      store_tiles(buf ^ 1);
      __syncthreads();
      buf ^= 1;
    }
  }

  #pragma unroll
  for (int mi = 0; mi < 4; mi++) {
    int r0 = bm + wm*64 + mi*16 + (lane >> 2);
    #pragma unroll
    for (int ni = 0; ni < 4; ni++) {
      int c0 = bn + wn*32 + ni*8 + ((lane & 3) << 1);
      float* p0 = C + (size_t)r0 * ldc;
      float* p1 = C + (size_t)(r0 + 8) * ldc;
      if (c0 < N) {
        float bv = __ldg(bias + c0);
        float v0 = acc[mi][ni][0] + bv;
        float v2 = acc[mi][ni][2] + bv;
        if (relu) { v0 = fmaxf(v0, 0.f); v2 = fmaxf(v2, 0.f); }
        p0[c0] = v0; p1[c0] = v2;
      }
      if (c0 + 1 < N) {
        float bv = __ldg(bias + c0 + 1);
        float v1 = acc[mi][ni][1] + bv;
        float v3 = acc[mi][ni][3] + bv;
        if (relu) { v1 = fmaxf(v1, 0.f); v3 = fmaxf(v3, 0.f); }
        p0[c0+1] = v1; p1[c0+1] = v3;
      }
    }
  }
}

// ---------------- tiled attention: block = (qtile of 32, head, batch) ----------
// Shared slot-0 keys (256) amortized across the 32 queries; own-block keys per q.
// smem floats: Qs[64][33] Ks[64][65] S[32][260] So[32][8] inv[32] + int kofs/mk[256]
#define ATTN_SMEM ((64*33 + 64*65 + 32*260 + 32*8 + 32)*4 + 512*4 + 64)
__global__ __launch_bounds__(256) void attn_kernel(const int* __restrict__ amask, int t)
{
  int qt = blockIdx.x, h = blockIdx.y, b = blockIdx.z;
  int tid = threadIdx.x, lane = tid & 31, w = tid >> 5;
  extern __shared__ char sm[];
  float* Qs   = (float*)sm;          // [64][33]  (e-major)
  float* Ks   = Qs + 64*33;          // [64][65]  (e-major)
  float* S    = Ks + 64*65;          // [32][260]
  float* So   = S + 32*260;          // [32][8]
  float* invs = So + 32*8;           // [32]
  int* kofs = (int*)(invs + 32);     // [256]
  int* mk   = kofs + 256;            // [256]

  int l0 = qt * 32;
  int slotQ = t - 1;

  if (tid < 256) {
    kofs[tid] = ((b*LL + tid)*6 + 0) * QKVLD;
    mk[tid]   = amask[b*LL + tid];
  }
  // load Q tile transposed: Qs[e][q]
  {
    int q = tid >> 3, e0 = (tid & 7) * 8;
    const float* qp = g_qkvc + ((size_t)((b*LL + l0 + q)*6 + slotQ))*QKVLD + h*64 + e0;
    #pragma unroll
    for (int i = 0; i < 8; i++) Qs[(e0+i)*33 + q] = qp[i];
  }
  __syncthreads();

  // ---- shared-key scores: 4 tiles of 64 keys ----
  int tq = tid >> 5, tk = tid & 31;
  for (int kt = 0; kt < 4; kt++) {
    {
      int k = tid >> 2, e0 = (tid & 3) * 16;
      const float* kp = g_qkvc + (size_t)kofs[kt*64 + k] + DD + h*64 + e0;
      #pragma unroll
      for (int i = 0; i < 16; i++) Ks[(e0+i)*65 + k] = kp[i];
    }
    __syncthreads();
    float acc[4][2] = {};
    #pragma unroll 8
    for (int e = 0; e < 64; e++) {
      float b0 = Ks[e*65 + tk], b1 = Ks[e*65 + tk + 32];
      #pragma unroll
      for (int i = 0; i < 4; i++) {
        float a = Qs[e*33 + tq*4 + i];
        acc[i][0] += a * b0;
        acc[i][1] += a * b1;
      }
    }
    int j0 = kt*64 + tk, j1 = j0 + 32;
    #pragma unroll
    for (int i = 0; i < 4; i++) {
      int q = tq*4 + i;
      S[q*260 + j0] = mk[j0] ? acc[i][0]*0.125f : -1e30f;
      S[q*260 + j1] = mk[j1] ? acc[i][1]*0.125f : -1e30f;
    }
    __syncthreads();
  }

  // ---- own-block key scores (slots 1..t-1) ----
  if (t > 1) {
    int tm1 = t - 1;
    int npairs = 32 * tm1;
    for (int p = w; p < npairs; p += 8) {
      int q = p / tm1, s = 1 + p % tm1;
      int row = b*LL + l0 + q;
      const float* kp = g_qkvc + ((size_t)(row*6 + s))*QKVLD + DD + h*64;
      float d = Qs[lane*33 + q] * kp[lane] + Qs[(lane+32)*33 + q] * kp[lane+32];
      #pragma unroll
      for (int o = 16; o; o >>= 1) d += __shfl_xor_sync(0xffffffffu, d, o);
      if (lane == 0) So[q*8 + s] = amask[row] ? d*0.125f : -1e30f;
    }
  }
  __syncthreads();

  // ---- softmax: warp w handles queries w*4..w*4+3 ----
  #pragma unroll
  for (int i = 0; i < 4; i++) {
    int q = w*4 + i;
    float m = -1e30f;
    #pragma unroll
    for (int jj = 0; jj < 8; jj++) m = fmaxf(m, S[q*260 + jj*32 + lane]);
    if (lane < t-1) m = fmaxf(m, So[q*8 + 1 + lane]);
    #pragma unroll
    for (int o = 16; o; o >>= 1) m = fmaxf(m, __shfl_xor_sync(0xffffffffu, m, o));
    float sum = 0.f;
    #pragma unroll
    for (int jj = 0; jj < 8; jj++) {
      int j = jj*32 + lane;
      float pp = __expf(S[q*260 + j] - m);
      S[q*260 + j] = pp;
      sum += pp;
    }
    if (lane < t-1) {
      float pp = __expf(So[q*8 + 1 + lane] - m);
      So[q*8 + 1 + lane] = pp;
      sum += pp;
    }
    #pragma unroll
    for (int o = 16; o; o >>= 1) sum += __shfl_xor_sync(0xffffffffu, sum, o);
    if (lane == 0) invs[q] = 1.f / sum;
  }
  __syncthreads();

  // ---- output: thread owns (4 q) x (2 e); V direct from gmem (L1-shared) ----
  float oacc[4][2] = {};
  #pragma unroll 4
  for (int j = 0; j < 256; j++) {
    const float2 v = *(const float2*)(g_qkvc + (size_t)kofs[j] + 2*DD + h*64 + lane*2);
    #pragma unroll
    for (int i = 0; i < 4; i++) {
      float pp = S[(tq*4+i)*260 + j];
      oacc[i][0] += pp * v.x;
      oacc[i][1] += pp * v.y;
    }
  }
  for (int s = 1; s < t; s++) {
    #pragma unroll
    for (int i = 0; i < 4; i++) {
      int q = tq*4 + i, row = b*LL + l0 + q;
      const float2 v = *(const float2*)(g_qkvc + ((size_t)(row*6 + s))*QKVLD + 2*DD + h*64 + lane*2);
      float pp = So[q*8 + s];
      oacc[i][0] += pp * v.x;
      oacc[i][1] += pp * v.y;
    }
  }
  #pragma unroll
  for (int i = 0; i < 4; i++) {
    int q = tq*4 + i, row = b*LL + l0 + q;
    float iv = invs[q];
    *(float2*)(g_attno + (size_t)row*DD + h*64 + lane*2) =
        make_float2(oacc[i][0]*iv, oacc[i][1]*iv);
  }
}

// ---------------- fused residual-add + LayerNorm (strided) ----------------
__global__ void add_ln_kernel(const float* __restrict__ A, int lda,
                              const float* __restrict__ R, int ldr,
                              const float* __restrict__ gma, const float* __restrict__ bta,
                              float* __restrict__ out, int ldo)
{
  int row = blockIdx.x;
  int tid = threadIdx.x;
  const float* pa = A + (size_t)row * lda;
  const float* pr = R + (size_t)row * ldr;
  float* po = out + (size_t)row * ldo;
  float v[3]; float s = 0.f, sq = 0.f;
  #pragma unroll
  for (int i = 0; i < 3; i++) {
    int idx = tid + i * 256;
    float xx = pa[idx] + pr[idx];
    v[i] = xx; s += xx; sq += xx * xx;
  }
  __shared__ float r1[8], r2[8];
  for (int o = 16; o; o >>= 1) {
    s  += __shfl_xor_sync(0xffffffffu, s, o);
    sq += __shfl_xor_sync(0xffffffffu, sq, o);
  }
  if ((tid & 31) == 0) { r1[tid >> 5] = s; r2[tid >> 5] = sq; }
  __syncthreads();
  s = 0.f; sq = 0.f;
  #pragma unroll
  for (int ww = 0; ww < 8; ww++) { s += r1[ww]; sq += r2[ww]; }
  float mean = s * (1.f / DD);
  float var  = sq * (1.f / DD) - mean * mean;
  float rinv = rsqrtf(var + 1e-5f);
  #pragma unroll
  for (int i = 0; i < 3; i++) {
    int idx = tid + i * 256;
    po[idx] = (v[i] - mean) * rinv * gma[idx] + bta[idx];
  }
}

// ---------------- host launch ----------------
extern "C" void kernel_launch(void* const* d_in, const int* in_sizes, int n_in,
                              void* d_out, int out_size)
{
  const int*   x     = (const int*)d_in[0];
  const int*   amask = (const int*)d_in[1];
  const float* emb   = (const float*)d_in[2];
  const float* pos   = (const float*)d_in[3];
  const float* temb  = (const float*)d_in[4];
  const float* ipw   = (const float*)d_in[5];
  const float* ipb   = (const float*)d_in[6];
  const float* aow   = (const float*)d_in[7];
  const float* aob   = (const float*)d_in[8];
  const float* ln1g  = (const float*)d_in[9];
  const float* ln1b  = (const float*)d_in[10];
  const float* w1    = (const float*)d_in[11];
  const float* b1    = (const float*)d_in[12];
  const float* w2    = (const float*)d_in[13];
  const float* b2    = (const float*)d_in[14];
  const float* ln2g  = (const float*)d_in[15];
  const float* ln2b  = (const float*)d_in[16];
  const float* hw    = (const float*)d_in[17];
  const float* hb    = (const float*)d_in[18];
  float* out = (float*)d_out;

  float *p_hbuf, *p_qkvc, *p_attno, *p_tmp, *p_y, *p_ff;
  cudaGetSymbolAddress((void**)&p_hbuf,  g_hbuf);
  cudaGetSymbolAddress((void**)&p_qkvc,  g_qkvc);
  cudaGetSymbolAddress((void**)&p_attno, g_attno);
  cudaGetSymbolAddress((void**)&p_tmp,   g_tmp);
  cudaGetSymbolAddress((void**)&p_y,     g_y);
  cudaGetSymbolAddress((void**)&p_ff,    g_ff);

  const int SM_BIG = (128+128)*256;
  const int SM_SML = (64+128)*256;
  cudaFuncSetAttribute(gemm_mma_kernel<128,128>,
                       cudaFuncAttributeMaxDynamicSharedMemorySize, SM_BIG);
  cudaFuncSetAttribute(gemm_mma_kernel<64,128>,
                       cudaFuncAttributeMaxDynamicSharedMemorySize, SM_SML);
  cudaFuncSetAttribute(attn_kernel,
                       cudaFuncAttributeMaxDynamicSharedMemorySize, ATTN_SMEM);

  embed_kernel<<<NROW, 256>>>(x, emb, pos);

  dim3 grid_sm(NROW/64, DD/128);
  dim3 grid_qkv(NROW/128, QKVLD/128);
  dim3 grid_attn(LL/32, HH, BB);

  for (int step = 0; step < NSTEPS; step++) {
    add_time_kernel<<<NROW, 256>>>(temb, step);

    const float* slotA = p_hbuf + (size_t)step * DD;

    gemm_mma_kernel<128,128><<<grid_qkv, 256, SM_BIG>>>(
        slotA, 7*DD, ipw, ipb, p_qkvc + (size_t)step*QKVLD, 6*QKVLD, QKVLD, 0);

    attn_kernel<<<grid_attn, 256, ATTN_SMEM>>>(amask, step + 1);

    gemm_mma_kernel<64,128><<<grid_sm, 128, SM_SML>>>(
        p_attno, DD, aow, aob, p_tmp, DD, DD, 0);
    add_ln_kernel<<<NROW, 256>>>(p_tmp, DD, slotA, 7*DD, ln1g, ln1b, p_y, DD);

    gemm_mma_kernel<64,128><<<grid_sm, 128, SM_SML>>>(
        p_y, DD, w1, b1, p_ff, DD, DD, 1);
    gemm_mma_kernel<64,128><<<grid_sm, 128, SM_SML>>>(
        p_ff, DD, w2, b2, p_tmp, DD, DD, 0);
    add_ln_kernel<<<NROW, 256>>>(p_tmp, DD, p_y, DD, ln2g, ln2b,
                                 p_hbuf + (size_t)(step + 1) * DD, 7*DD);
  }

  dim3 grid_head(NROW/128, (CC + 127)/128);
  gemm_mma_kernel<128,128><<<grid_head, 256, SM_BIG>>>(
      p_hbuf + (size_t)6*DD, 7*DD, hw, hb, out, CC, CC, 0);
}